// round 5
// baseline (speedup 1.0000x reference)
#include <cuda_runtime.h>
#include <cuda_fp16.h>

#define N_NODES 50000
#define N_EDGES 800000
#define F_IN    128
#define F_HID   64
#define SCAN_B  1024
#define SCAN_NB ((N_NODES + SCAN_B - 1) / SCAN_B)   // 49

typedef unsigned long long ull;

// ---------------- scratch (no allocations allowed) ----------------
__device__ int   g_deg_out_i[N_NODES];   // zero-initialized at load; re-zeroed by scanC each call
__device__ int   g_deg_in_i [N_NODES];
__device__ float g_norm_out[N_NODES];
__device__ float g_norm_in [N_NODES];
__device__ int   g_off    [N_NODES + 1];
__device__ int   g_cursor [N_NODES];
__device__ int   g_bsum   [64];
__device__ int   g_bpre   [64];
__device__ int   g_ticket;               // reset by scanA's last block
__device__ int   g_csr_src[N_EDGES];
__device__ __align__(16) __half g_h[N_NODES * F_HID];  // gemm output (fp16 storage)
__device__ __align__(16) float  g_t[N_NODES * F_HID];  // post-layer1 acts (pre-scaled, fp32)

// ---------------- degree ----------------
__global__ void count_deg_kernel(const int* __restrict__ src, const int* __restrict__ dst) {
    int e = blockIdx.x * blockDim.x + threadIdx.x;
    if (e < N_EDGES) {
        atomicAdd(&g_deg_out_i[src[e]], 1);
        atomicAdd(&g_deg_in_i [dst[e]], 1);
    }
}

// ---------------- scan phase A: per-block scan + last block scans block sums ----------------
__global__ void __launch_bounds__(SCAN_B) scanA_kernel() {
    __shared__ int warp_sums[32];
    __shared__ int is_last;
    int tid = threadIdx.x;
    int lane = tid & 31, wid = tid >> 5;
    int i = blockIdx.x * SCAN_B + tid;
    int v = (i < N_NODES) ? g_deg_in_i[i] : 0;
    int x = v;
#pragma unroll
    for (int o = 1; o < 32; o <<= 1) {
        int y = __shfl_up_sync(0xffffffffu, x, o);
        if (lane >= o) x += y;
    }
    if (lane == 31) warp_sums[wid] = x;
    __syncthreads();
    if (wid == 0) {
        int s = warp_sums[lane];
#pragma unroll
        for (int o = 1; o < 32; o <<= 1) {
            int y = __shfl_up_sync(0xffffffffu, s, o);
            if (lane >= o) s += y;
        }
        warp_sums[lane] = s;
    }
    __syncthreads();
    int excl = (wid ? warp_sums[wid - 1] : 0) + x - v;
    if (i < N_NODES) g_off[i] = excl;
    if (tid == SCAN_B - 1) {
        g_bsum[blockIdx.x] = excl + v;
        __threadfence();
    }
    __syncthreads();
    if (tid == 0)
        is_last = (atomicAdd(&g_ticket, 1) == (int)gridDim.x - 1);
    __syncthreads();
    if (is_last && wid == 0) {
        __threadfence();
        int acc = 0;
        for (int b = 0; b < SCAN_NB; b += 32) {
            int t = b + lane;
            int bv = (t < SCAN_NB) ? g_bsum[t] : 0;
            int bx = bv;
#pragma unroll
            for (int o = 1; o < 32; o <<= 1) {
                int y = __shfl_up_sync(0xffffffffu, bx, o);
                if (lane >= o) bx += y;
            }
            if (t < SCAN_NB) g_bpre[t] = acc + bx - bv;
            acc += __shfl_sync(0xffffffffu, bx, 31);
        }
        if (lane == 0) g_ticket = 0;   // reset for next call
    }
}

// ---------------- scan phase C: finalize offsets + cursors + norms; re-zero degrees ----------------
__global__ void __launch_bounds__(SCAN_B) scanC_kernel() {
    int i = blockIdx.x * SCAN_B + threadIdx.x;
    if (i < N_NODES) {
        int off = g_off[i] + g_bpre[blockIdx.x];
        g_off[i] = off;
        g_cursor[i] = off;
        g_norm_out[i] = rsqrtf(fmaxf((float)g_deg_out_i[i], 1.f));
        g_norm_in [i] = rsqrtf(fmaxf((float)g_deg_in_i [i], 1.f));
        g_deg_out_i[i] = 0;            // ready for next call
        g_deg_in_i [i] = 0;
    }
    if (i == 0) g_off[N_NODES] = N_EDGES;
}

// ---------------- CSR fill: csr_src grouped by dst ----------------
__global__ void fill_kernel(const int* __restrict__ src, const int* __restrict__ dst) {
    int e = blockIdx.x * blockDim.x + threadIdx.x;
    if (e < N_EDGES) {
        int pos = atomicAdd(&g_cursor[dst[e]], 1);
        g_csr_src[pos] = src[e];
    }
}

// ---------------- helpers ----------------
__device__ __forceinline__ ull pack_dup(float a) {
    ull r;
    asm("mov.b64 %0, {%1, %1};" : "=l"(r) : "f"(a));
    return r;
}
__device__ __forceinline__ ull pack2(float a, float b) {
    ull r;
    asm("mov.b64 %0, {%1, %2};" : "=l"(r) : "f"(a), "f"(b));
    return r;
}
__device__ __forceinline__ float2 unpack2(ull v) {
    float x, y;
    asm("mov.b64 {%0, %1}, %2;" : "=f"(x), "=f"(y) : "l"(v));
    return make_float2(x, y);
}
__device__ __forceinline__ void ffma2(ull& acc, ull a, ull w) {
    asm("fma.rn.f32x2 %0, %1, %2, %0;" : "+l"(acc) : "l"(a), "l"(w));
}
__device__ __forceinline__ void store_half4_p(__half* base, float2 lo, float2 hi) {
    union { __half2 h[2]; uint2 u; } pk;
    pk.h[0] = __floats2half2_rn(lo.x, lo.y);
    pk.h[1] = __floats2half2_rn(hi.x, hi.y);
    *reinterpret_cast<uint2*>(base) = pk.u;
}

// ---------------- GEMM1: g_h = fp16((x * norm_out) @ W1)  (K=128, N=64), FFMA2 ----------------
__global__ void __launch_bounds__(256) gemm1_kernel(const float* __restrict__ x,
                                                    const float* __restrict__ W) {
    __shared__ float Ws[F_IN * F_HID];    // 32 KB
    __shared__ float xs[64 * 129];        // 33 KB, pad->conflict-free
    int tid = threadIdx.x;
    for (int i = tid; i < F_IN * F_HID / 4; i += 256)
        ((float4*)Ws)[i] = ((const float4*)W)[i];
    int row0 = blockIdx.x * 64;
    for (int i = tid; i < 64 * 32; i += 256) {
        int r = i >> 5, kq = i & 31;
        int row = row0 + r;
        float4 v = make_float4(0.f, 0.f, 0.f, 0.f);
        float s = 0.f;
        if (row < N_NODES) {
            v = ((const float4*)x)[row * 32 + kq];
            s = g_norm_out[row];
        }
        float* p = &xs[r * 129 + kq * 4];
        p[0] = v.x * s; p[1] = v.y * s; p[2] = v.z * s; p[3] = v.w * s;
    }
    __syncthreads();
    int rg = tid >> 4;       // rows rg + 16j
    int fg = tid & 15;       // feature quad
    ull acc01[4], acc23[4];  // per row j: features (x,y) and (z,w)
#pragma unroll
    for (int j = 0; j < 4; j++) { acc01[j] = 0ULL; acc23[j] = 0ULL; }
    const float4* Ws4 = (const float4*)Ws;
#pragma unroll 4
    for (int k = 0; k < F_IN; k++) {
        float4 w = Ws4[k * 16 + fg];
        ull w01 = pack2(w.x, w.y);
        ull w23 = pack2(w.z, w.w);
#pragma unroll
        for (int j = 0; j < 4; j++) {
            ull aa = pack_dup(xs[(rg + 16 * j) * 129 + k]);
            ffma2(acc01[j], aa, w01);
            ffma2(acc23[j], aa, w23);
        }
    }
#pragma unroll
    for (int j = 0; j < 4; j++) {
        int row = row0 + rg + 16 * j;
        if (row < N_NODES)
            store_half4_p(&g_h[row * F_HID + fg * 4], unpack2(acc01[j]), unpack2(acc23[j]));
    }
}

// ---------------- GEMM2: g_h = fp16(g_t @ W2)  (K=64, N=64), FFMA2 ----------------
__global__ void __launch_bounds__(256) gemm2_kernel(const float* __restrict__ W) {
    __shared__ float Ws[F_HID * F_HID];   // 16 KB
    __shared__ float xs[64 * 65];         // 16.6 KB
    int tid = threadIdx.x;
    for (int i = tid; i < F_HID * F_HID / 4; i += 256)
        ((float4*)Ws)[i] = ((const float4*)W)[i];
    int row0 = blockIdx.x * 64;
    for (int i = tid; i < 64 * 16; i += 256) {
        int r = i >> 4, kq = i & 15;
        int row = row0 + r;
        float4 v = make_float4(0.f, 0.f, 0.f, 0.f);
        if (row < N_NODES) v = ((const float4*)g_t)[row * 16 + kq];
        float* p = &xs[r * 65 + kq * 4];
        p[0] = v.x; p[1] = v.y; p[2] = v.z; p[3] = v.w;
    }
    __syncthreads();
    int rg = tid >> 4;
    int fg = tid & 15;
    ull acc01[4], acc23[4];
#pragma unroll
    for (int j = 0; j < 4; j++) { acc01[j] = 0ULL; acc23[j] = 0ULL; }
    const float4* Ws4 = (const float4*)Ws;
#pragma unroll 4
    for (int k = 0; k < F_HID; k++) {
        float4 w = Ws4[k * 16 + fg];
        ull w01 = pack2(w.x, w.y);
        ull w23 = pack2(w.z, w.w);
#pragma unroll
        for (int j = 0; j < 4; j++) {
            ull aa = pack_dup(xs[(rg + 16 * j) * 65 + k]);
            ffma2(acc01[j], aa, w01);
            ffma2(acc23[j], aa, w23);
        }
    }
#pragma unroll
    for (int j = 0; j < 4; j++) {
        int row = row0 + rg + 16 * j;
        if (row < N_NODES)
            store_half4_p(&g_h[row * F_HID + fg * 4], unpack2(acc01[j]), unpack2(acc23[j]));
    }
}

// ---------------- gather core: 16 lanes per edge, 2 edges per warp instruction ----------------
// lanes 0-15 handle even edge, 16-31 odd edge; each lane covers 4 features (8B fp16).
__device__ __forceinline__ float4 gather_node(int node, int half, int fl) {
    int beg = g_off[node], end = g_off[node + 1];
    const uint2* h4 = (const uint2*)g_h;   // 8 bytes = 4 halves
    float4 a = make_float4(0.f, 0.f, 0.f, 0.f);
    float4 b = make_float4(0.f, 0.f, 0.f, 0.f);
    int j = beg;
    for (; j + 3 < end; j += 4) {
        int s0 = __ldg(&g_csr_src[j + half]);
        int s1 = __ldg(&g_csr_src[j + 2 + half]);
        uint2 r0 = h4[s0 * 16 + fl];
        uint2 r1 = h4[s1 * 16 + fl];
        float2 p0 = __half22float2(*(__half2*)&r0.x);
        float2 p1 = __half22float2(*(__half2*)&r0.y);
        float2 q0 = __half22float2(*(__half2*)&r1.x);
        float2 q1 = __half22float2(*(__half2*)&r1.y);
        a.x += p0.x; a.y += p0.y; a.z += p1.x; a.w += p1.y;
        b.x += q0.x; b.y += q0.y; b.z += q1.x; b.w += q1.y;
    }
    if (j + 1 < end) {
        int s = __ldg(&g_csr_src[j + half]);
        uint2 r = h4[s * 16 + fl];
        float2 p0 = __half22float2(*(__half2*)&r.x);
        float2 p1 = __half22float2(*(__half2*)&r.y);
        a.x += p0.x; a.y += p0.y; a.z += p1.x; a.w += p1.y;
        j += 2;
    }
    if (j < end && half == 0) {
        int s = __ldg(&g_csr_src[j]);
        uint2 r = h4[s * 16 + fl];
        float2 p0 = __half22float2(*(__half2*)&r.x);
        float2 p1 = __half22float2(*(__half2*)&r.y);
        a.x += p0.x; a.y += p0.y; a.z += p1.x; a.w += p1.y;
    }
    a.x += b.x; a.y += b.y; a.z += b.z; a.w += b.w;
    // combine halves
    a.x += __shfl_xor_sync(0xffffffffu, a.x, 16);
    a.y += __shfl_xor_sync(0xffffffffu, a.y, 16);
    a.z += __shfl_xor_sync(0xffffffffu, a.z, 16);
    a.w += __shfl_xor_sync(0xffffffffu, a.w, 16);
    return a;
}

// ---------------- gather layer 1: g_t = relu(sum*norm_in + b1) * norm_out ----------------
__global__ void __launch_bounds__(256) gather1_kernel(const float* __restrict__ b1) {
    int node = blockIdx.x * 8 + (threadIdx.x >> 5);
    int lane = threadIdx.x & 31;
    if (node >= N_NODES) return;
    int half = lane >> 4, fl = lane & 15;
    float4 a = gather_node(node, half, fl);
    if (half == 0) {
        float ni = g_norm_in[node], no = g_norm_out[node];
        float4 bb = ((const float4*)b1)[fl];
        float4 o;
        o.x = fmaxf(a.x * ni + bb.x, 0.f) * no;
        o.y = fmaxf(a.y * ni + bb.y, 0.f) * no;
        o.z = fmaxf(a.z * ni + bb.z, 0.f) * no;
        o.w = fmaxf(a.w * ni + bb.w, 0.f) * no;
        ((float4*)g_t)[node * 16 + fl] = o;
    }
}

// ---------------- gather layer 2: out = sum*norm_in + b2 ----------------
__global__ void __launch_bounds__(256) gather2_kernel(const float* __restrict__ b2,
                                                      float* __restrict__ out) {
    int node = blockIdx.x * 8 + (threadIdx.x >> 5);
    int lane = threadIdx.x & 31;
    if (node >= N_NODES) return;
    int half = lane >> 4, fl = lane & 15;
    float4 a = gather_node(node, half, fl);
    if (half == 0) {
        float ni = g_norm_in[node];
        float4 bb = ((const float4*)b2)[fl];
        float4 o;
        o.x = a.x * ni + bb.x;
        o.y = a.y * ni + bb.y;
        o.z = a.z * ni + bb.z;
        o.w = a.w * ni + bb.w;
        ((float4*)out)[node * 16 + fl] = o;
    }
}

extern "C" void kernel_launch(void* const* d_in, const int* in_sizes, int n_in,
                              void* d_out, int out_size) {
    const float* x   = (const float*)d_in[0];
    const int*   src = (const int*)  d_in[1];
    const int*   dst = (const int*)  d_in[2];
    const float* W1  = (const float*)d_in[3];
    const float* b1  = (const float*)d_in[4];
    const float* W2  = (const float*)d_in[5];
    const float* b2  = (const float*)d_in[6];
    float* out = (float*)d_out;

    const int T = 256;
    const int edgeBlocks   = (N_EDGES + T - 1) / T;   // 3125
    const int gemmBlocks   = (N_NODES + 63) / 64;     // 782
    const int gatherBlocks = (N_NODES + 7) / 8;       // 6250

    // degrees, norms, CSR
    count_deg_kernel<<<edgeBlocks, T>>>(src, dst);
    scanA_kernel<<<SCAN_NB, SCAN_B>>>();
    scanC_kernel<<<SCAN_NB, SCAN_B>>>();
    fill_kernel<<<edgeBlocks, T>>>(src, dst);

    // layer 1
    gemm1_kernel<<<gemmBlocks, T>>>(x, W1);
    gather1_kernel<<<gatherBlocks, T>>>(b1);

    // layer 2
    gemm2_kernel<<<gemmBlocks, T>>>(W2);
    gather2_kernel<<<gatherBlocks, T>>>(b2, out);
}

// round 7
// speedup vs baseline: 1.4013x; 1.4013x over previous
#include <cuda_runtime.h>

#define N_NODES 50000
#define N_EDGES 800000
#define F_IN    128
#define F_HID   64
#define SCAN_B  1024
#define SCAN_NB ((N_NODES + SCAN_B - 1) / SCAN_B)   // 49

// ---------------- scratch (no allocations allowed) ----------------
__device__ int   g_deg_out_i[N_NODES];   // zeroed at load; re-zeroed by scanC each call
__device__ int   g_deg_in_i [N_NODES];
__device__ float g_norm_out[N_NODES];
__device__ float g_norm_in [N_NODES];
__device__ int   g_off    [N_NODES + 1];
__device__ int   g_cursor [N_NODES];
__device__ int   g_bsum   [64];
__device__ int   g_bpre   [64];
__device__ int   g_ticket;               // reset by scanA's last block
__device__ int   g_csr_src[N_EDGES];
__device__ __align__(16) float g_h[N_NODES * F_HID];   // gemm output
__device__ __align__(16) float g_t[N_NODES * F_HID];   // post-layer1 acts (pre-scaled)

// ---------------- degree ----------------
__global__ void count_deg_kernel(const int* __restrict__ src, const int* __restrict__ dst) {
    int e = blockIdx.x * blockDim.x + threadIdx.x;
    if (e < N_EDGES) {
        atomicAdd(&g_deg_out_i[src[e]], 1);
        atomicAdd(&g_deg_in_i [dst[e]], 1);
    }
}

// ---------------- scan phase A: per-block scan + last block scans block sums ----------------
__global__ void __launch_bounds__(SCAN_B) scanA_kernel() {
    __shared__ int warp_sums[32];
    __shared__ int is_last;
    int tid = threadIdx.x;
    int lane = tid & 31, wid = tid >> 5;
    int i = blockIdx.x * SCAN_B + tid;
    int v = (i < N_NODES) ? g_deg_in_i[i] : 0;
    int x = v;
#pragma unroll
    for (int o = 1; o < 32; o <<= 1) {
        int y = __shfl_up_sync(0xffffffffu, x, o);
        if (lane >= o) x += y;
    }
    if (lane == 31) warp_sums[wid] = x;
    __syncthreads();
    if (wid == 0) {
        int s = warp_sums[lane];
#pragma unroll
        for (int o = 1; o < 32; o <<= 1) {
            int y = __shfl_up_sync(0xffffffffu, s, o);
            if (lane >= o) s += y;
        }
        warp_sums[lane] = s;
    }
    __syncthreads();
    int excl = (wid ? warp_sums[wid - 1] : 0) + x - v;
    if (i < N_NODES) g_off[i] = excl;
    if (tid == SCAN_B - 1) {
        g_bsum[blockIdx.x] = excl + v;
        __threadfence();
    }
    __syncthreads();
    if (tid == 0)
        is_last = (atomicAdd(&g_ticket, 1) == (int)gridDim.x - 1);
    __syncthreads();
    if (is_last && wid == 0) {
        __threadfence();
        int acc = 0;
        for (int b = 0; b < SCAN_NB; b += 32) {
            int t = b + lane;
            int bv = (t < SCAN_NB) ? g_bsum[t] : 0;
            int bx = bv;
#pragma unroll
            for (int o = 1; o < 32; o <<= 1) {
                int y = __shfl_up_sync(0xffffffffu, bx, o);
                if (lane >= o) bx += y;
            }
            if (t < SCAN_NB) g_bpre[t] = acc + bx - bv;
            acc += __shfl_sync(0xffffffffu, bx, 31);
        }
        if (lane == 0) g_ticket = 0;   // reset for next call
    }
}

// ---------------- scan phase C: finalize offsets + cursors + norms; re-zero degrees ----------------
__global__ void __launch_bounds__(SCAN_B) scanC_kernel() {
    int i = blockIdx.x * SCAN_B + threadIdx.x;
    if (i < N_NODES) {
        int off = g_off[i] + g_bpre[blockIdx.x];
        g_off[i] = off;
        g_cursor[i] = off;
        g_norm_out[i] = rsqrtf(fmaxf((float)g_deg_out_i[i], 1.f));
        g_norm_in [i] = rsqrtf(fmaxf((float)g_deg_in_i [i], 1.f));
        g_deg_out_i[i] = 0;            // ready for next call
        g_deg_in_i [i] = 0;
    }
    if (i == 0) g_off[N_NODES] = N_EDGES;
}

// ---------------- CSR fill: csr_src grouped by dst ----------------
__global__ void fill_kernel(const int* __restrict__ src, const int* __restrict__ dst) {
    int e = blockIdx.x * blockDim.x + threadIdx.x;
    if (e < N_EDGES) {
        int pos = atomicAdd(&g_cursor[dst[e]], 1);
        g_csr_src[pos] = src[e];
    }
}

// ---------------- GEMM1: g_h = (x * norm_out) @ W1  (K=128, N=64) ----------------
__global__ void __launch_bounds__(256) gemm1_kernel(const float* __restrict__ x,
                                                    const float* __restrict__ W) {
    __shared__ float Ws[F_IN * F_HID];    // 32 KB
    __shared__ float xs[64 * 129];        // 33 KB, pad->conflict-free
    int tid = threadIdx.x;
    for (int i = tid; i < F_IN * F_HID / 4; i += 256)
        ((float4*)Ws)[i] = ((const float4*)W)[i];
    int row0 = blockIdx.x * 64;
    for (int i = tid; i < 64 * 32; i += 256) {
        int r = i >> 5, kq = i & 31;
        int row = row0 + r;
        float4 v = make_float4(0.f, 0.f, 0.f, 0.f);
        float s = 0.f;
        if (row < N_NODES) {
            v = ((const float4*)x)[row * 32 + kq];
            s = g_norm_out[row];
        }
        float* p = &xs[r * 129 + kq * 4];
        p[0] = v.x * s; p[1] = v.y * s; p[2] = v.z * s; p[3] = v.w * s;
    }
    __syncthreads();
    int rg = tid >> 4;       // 0..15, rows rg + 16j
    int fg = tid & 15;       // feature quad
    float4 acc[4];
#pragma unroll
    for (int j = 0; j < 4; j++) acc[j] = make_float4(0.f, 0.f, 0.f, 0.f);
    const float4* Ws4 = (const float4*)Ws;
#pragma unroll 4
    for (int k = 0; k < F_IN; k++) {
        float4 w = Ws4[k * 16 + fg];
#pragma unroll
        for (int j = 0; j < 4; j++) {
            float a = xs[(rg + 16 * j) * 129 + k];
            acc[j].x += a * w.x; acc[j].y += a * w.y;
            acc[j].z += a * w.z; acc[j].w += a * w.w;
        }
    }
#pragma unroll
    for (int j = 0; j < 4; j++) {
        int row = row0 + rg + 16 * j;
        if (row < N_NODES) ((float4*)g_h)[row * 16 + fg] = acc[j];
    }
}

// ---------------- GEMM2: g_h = g_t @ W2  (K=64, N=64) ----------------
__global__ void __launch_bounds__(256) gemm2_kernel(const float* __restrict__ W) {
    __shared__ float Ws[F_HID * F_HID];   // 16 KB
    __shared__ float xs[64 * 65];         // 16.6 KB
    int tid = threadIdx.x;
    for (int i = tid; i < F_HID * F_HID / 4; i += 256)
        ((float4*)Ws)[i] = ((const float4*)W)[i];
    int row0 = blockIdx.x * 64;
    for (int i = tid; i < 64 * 16; i += 256) {
        int r = i >> 4, kq = i & 15;
        int row = row0 + r;
        float4 v = make_float4(0.f, 0.f, 0.f, 0.f);
        if (row < N_NODES) v = ((const float4*)g_t)[row * 16 + kq];
        float* p = &xs[r * 65 + kq * 4];
        p[0] = v.x; p[1] = v.y; p[2] = v.z; p[3] = v.w;
    }
    __syncthreads();
    int rg = tid >> 4;
    int fg = tid & 15;
    float4 acc[4];
#pragma unroll
    for (int j = 0; j < 4; j++) acc[j] = make_float4(0.f, 0.f, 0.f, 0.f);
    const float4* Ws4 = (const float4*)Ws;
#pragma unroll 4
    for (int k = 0; k < F_HID; k++) {
        float4 w = Ws4[k * 16 + fg];
#pragma unroll
        for (int j = 0; j < 4; j++) {
            float a = xs[(rg + 16 * j) * 65 + k];
            acc[j].x += a * w.x; acc[j].y += a * w.y;
            acc[j].z += a * w.z; acc[j].w += a * w.w;
        }
    }
#pragma unroll
    for (int j = 0; j < 4; j++) {
        int row = row0 + rg + 16 * j;
        if (row < N_NODES) ((float4*)g_h)[row * 16 + fg] = acc[j];
    }
}

// ---------------- gather layer 1: g_t = relu(sum(h[src])*norm_in + b1) * norm_out ----------------
__global__ void __launch_bounds__(256) gather1_kernel(const float* __restrict__ b1) {
    int node = blockIdx.x * 8 + (threadIdx.x >> 5);
    int lane = threadIdx.x & 31;
    if (node >= N_NODES) return;
    int beg = g_off[node], end = g_off[node + 1];
    const float2* h2 = (const float2*)g_h;
    float ax = 0.f, ay = 0.f, bx = 0.f, by = 0.f;
    int j = beg;
    for (; j + 1 < end; j += 2) {
        int s0 = __ldg(&g_csr_src[j]);
        int s1 = __ldg(&g_csr_src[j + 1]);
        float2 v0 = h2[s0 * 32 + lane];
        float2 v1 = h2[s1 * 32 + lane];
        ax += v0.x; ay += v0.y;
        bx += v1.x; by += v1.y;
    }
    if (j < end) {
        int s = __ldg(&g_csr_src[j]);
        float2 v = h2[s * 32 + lane];
        ax += v.x; ay += v.y;
    }
    ax += bx; ay += by;
    float ni = g_norm_in[node], no = g_norm_out[node];
    float2 bb = ((const float2*)b1)[lane];
    float2 o;
    o.x = fmaxf(ax * ni + bb.x, 0.f) * no;
    o.y = fmaxf(ay * ni + bb.y, 0.f) * no;
    ((float2*)g_t)[node * 32 + lane] = o;
}

// ---------------- gather layer 2: out = sum(h[src])*norm_in + b2 ----------------
__global__ void __launch_bounds__(256) gather2_kernel(const float* __restrict__ b2,
                                                      float* __restrict__ out) {
    int node = blockIdx.x * 8 + (threadIdx.x >> 5);
    int lane = threadIdx.x & 31;
    if (node >= N_NODES) return;
    int beg = g_off[node], end = g_off[node + 1];
    const float2* h2 = (const float2*)g_h;
    float ax = 0.f, ay = 0.f, bx = 0.f, by = 0.f;
    int j = beg;
    for (; j + 1 < end; j += 2) {
        int s0 = __ldg(&g_csr_src[j]);
        int s1 = __ldg(&g_csr_src[j + 1]);
        float2 v0 = h2[s0 * 32 + lane];
        float2 v1 = h2[s1 * 32 + lane];
        ax += v0.x; ay += v0.y;
        bx += v1.x; by += v1.y;
    }
    if (j < end) {
        int s = __ldg(&g_csr_src[j]);
        float2 v = h2[s * 32 + lane];
        ax += v.x; ay += v.y;
    }
    ax += bx; ay += by;
    float ni = g_norm_in[node];
    float2 bb = ((const float2*)b2)[lane];
    float2 o;
    o.x = ax * ni + bb.x;
    o.y = ay * ni + bb.y;
    ((float2*)out)[node * 32 + lane] = o;
}

extern "C" void kernel_launch(void* const* d_in, const int* in_sizes, int n_in,
                              void* d_out, int out_size) {
    const float* x   = (const float*)d_in[0];
    const int*   src = (const int*)  d_in[1];
    const int*   dst = (const int*)  d_in[2];
    const float* W1  = (const float*)d_in[3];
    const float* b1  = (const float*)d_in[4];
    const float* W2  = (const float*)d_in[5];
    const float* b2  = (const float*)d_in[6];
    float* out = (float*)d_out;

    const int T = 256;
    const int edgeBlocks   = (N_EDGES + T - 1) / T;   // 3125
    const int gemmBlocks   = (N_NODES + 63) / 64;     // 782
    const int gatherBlocks = (N_NODES + 7) / 8;       // 6250

    // degrees, norms, CSR
    count_deg_kernel<<<edgeBlocks, T>>>(src, dst);
    scanA_kernel<<<SCAN_NB, SCAN_B>>>();
    scanC_kernel<<<SCAN_NB, SCAN_B>>>();
    fill_kernel<<<edgeBlocks, T>>>(src, dst);

    // layer 1
    gemm1_kernel<<<gemmBlocks, T>>>(x, W1);
    gather1_kernel<<<gatherBlocks, T>>>(b1);

    // layer 2
    gemm2_kernel<<<gemmBlocks, T>>>(W2);
    gather2_kernel<<<gatherBlocks, T>>>(b2, out);
}